// round 2
// baseline (speedup 1.0000x reference)
#include <cuda_runtime.h>
#include <cuda_bf16.h>

// ---------------------------------------------------------------------------
// SimpleLSTM on GB300 (sm_103a).
//
// Decomposition:
//   G = [H_t, x_t] @ W^T + b  splits into  G_h(H_t) + G_x(token).
//   G_x depends only on the token id -> precompute token table
//       T[v][g] = E[v] . W[grow(g), 256:512] + b[grow(g)]
//   for the 768 LIVE gate rows only (F, O, Htmp -- the I gate is dead code
//   in the reference).
//
//   kernel 1 (table_kernel): the 32000x768x256 table GEMM; block (0,0) also
//       zeroes the H double buffer and the step-barrier counter.
//   kernel 2 (lstm_kernel): persistent, 128 CTAs = 16 batch-tiles x 8
//       col-tiles, W_h slice (96 rows x 256) resident in SMEM, C-state in
//       SMEM, H exchanged via global double buffer + atomic step barrier.
// ---------------------------------------------------------------------------

#define NB    128
#define LSEQ  2048
#define HDIM  256
#define EMB   256
#define VOC   32000
#define G3    768            // 3 live gates * 256 columns

// ---- device-global state (static allocation; no cudaMalloc) ---------------
__device__ float    g_T[VOC * G3];          // token-gate table (~98.3 MB)
__device__ float    g_Hbuf[2][NB * HDIM];   // H double buffer
__device__ unsigned g_ctr;                  // monotonic step barrier counter

// ---------------------------------------------------------------------------
// helpers
// ---------------------------------------------------------------------------
__device__ __forceinline__ unsigned long long ffma2(unsigned long long a,
                                                    unsigned long long b,
                                                    unsigned long long c)
{
    unsigned long long d;
    asm("fma.rn.f32x2 %0, %1, %2, %3;" : "=l"(d) : "l"(a), "l"(b), "l"(c));
    return d;
}

__device__ __forceinline__ float2 ull2f2(unsigned long long v)
{
    float2 f;
    asm("mov.b64 {%0, %1}, %2;" : "=f"(f.x), "=f"(f.y) : "l"(v));
    return f;
}

__device__ __forceinline__ unsigned ld_acq(const unsigned* p)
{
    unsigned v;
    asm volatile("ld.acquire.gpu.u32 %0, [%1];" : "=r"(v) : "l"(p) : "memory");
    return v;
}

__device__ __forceinline__ void red_add_rel(unsigned* p, unsigned v)
{
    asm volatile("red.add.release.gpu.u32 [%0], %1;" :: "l"(p), "r"(v) : "memory");
}

__device__ __forceinline__ float sigmoidf_(float x)
{
    return 1.0f / (1.0f + expf(-x));
}

// ---------------------------------------------------------------------------
// Kernel 1: token table GEMM  (M=32000 tokens, N=768 live gates, K=256).
// 64x64 tile per block, 256 threads, 4x4 accumulators per thread.
// ---------------------------------------------------------------------------
__global__ void table_kernel(const float* __restrict__ E,
                             const float* __restrict__ Ww,
                             const float* __restrict__ Wb)
{
    __shared__ float Esm[32][68];
    __shared__ float Wsm[32][68];

    const int tid = threadIdx.x;
    const int v0  = blockIdx.x * 64;
    const int g0  = blockIdx.y * 64;

    // block (0,0) also resets the recurrent state for this launch
    if (blockIdx.x == 0 && blockIdx.y == 0) {
        float* hb = (float*)g_Hbuf;
        for (int i = tid; i < 2 * NB * HDIM; i += 256) hb[i] = 0.0f;
        if (tid == 0) g_ctr = 0u;
    }

    const int tx = tid & 15;    // gate-column sub-tile
    const int ty = tid >> 4;    // token-row sub-tile

    float acc[4][4];
#pragma unroll
    for (int i = 0; i < 4; i++)
#pragma unroll
        for (int j = 0; j < 4; j++) acc[i][j] = 0.0f;

    for (int kb = 0; kb < 8; kb++) {
        for (int i = tid; i < 64 * 32; i += 256) {
            int row = i >> 5, kk = i & 31;
            Esm[kk][row] = E[(v0 + row) * EMB + kb * 32 + kk];
            int gg   = g0 + row;
            int gate = gg >> 8, jj = gg & 255;
            int grow = (gate == 0 ? 0 : (gate == 1 ? 512 : 768)) + jj;
            Wsm[kk][row] = Ww[grow * 512 + 256 + kb * 32 + kk];
        }
        __syncthreads();
#pragma unroll
        for (int kk = 0; kk < 32; kk++) {
            float4 a4 = *(const float4*)&Esm[kk][ty * 4];
            float4 b4 = *(const float4*)&Wsm[kk][tx * 4];
            float av[4] = {a4.x, a4.y, a4.z, a4.w};
            float bv[4] = {b4.x, b4.y, b4.z, b4.w};
#pragma unroll
            for (int i = 0; i < 4; i++)
#pragma unroll
                for (int j = 0; j < 4; j++) acc[i][j] += av[i] * bv[j];
        }
        __syncthreads();
    }

#pragma unroll
    for (int i = 0; i < 4; i++) {
        int v = v0 + ty * 4 + i;
#pragma unroll
        for (int j = 0; j < 4; j++) {
            int g    = g0 + tx * 4 + j;
            int gate = g >> 8, jj = g & 255;
            int grow = (gate == 0 ? 0 : (gate == 1 ? 512 : 768)) + jj;
            g_T[v * G3 + g] = acc[i][j] + Wb[grow];
        }
    }
}

// ---------------------------------------------------------------------------
// Kernel 2: persistent recurrent kernel.
//   grid = 128 CTAs (bt = blockIdx.x>>3 : 8-row batch tile;
//                    ct = blockIdx.x&7  : 32-col hidden tile)
//   block = 192 threads = 6 warps: warp w -> cg = w%3 (F/O/Htmp), kh = w/3
//   (k-half 0/1). Thread computes one gate column over one k-half.
// ---------------------------------------------------------------------------

// dynamic SMEM layout (bytes)
#define SM_W    0          // ulonglong2 Wsm[64*96]   : 98304  [k4*96 + col] = W[col][4k4..+3]
#define SM_H    98304      // ulonglong2 Hsm[8*64]    : 8192   [r*64 + k4]   = H[r][4k4..+3]
#define SM_G    106496     // float  Gsm[2*8*96]      : 6144   [(kh*8+r)*96 + col]
#define SM_C    112640     // float  Csm[8*32]        : 1024
#define SM_TOK  113664     // int    tok[8]           : 32
#define SMEM_TOTAL 113696

__global__ void __launch_bounds__(192, 1)
lstm_kernel(const void* __restrict__ Xraw,
            const float* __restrict__ Ww,
            float* __restrict__ out)
{
    extern __shared__ char smem[];
    ulonglong2* Wsm = (ulonglong2*)(smem + SM_W);
    ulonglong2* Hsm = (ulonglong2*)(smem + SM_H);
    float*      Gsm = (float*)(smem + SM_G);
    float*      Csm = (float*)(smem + SM_C);
    int*        tok = (int*)(smem + SM_TOK);

    const int tid  = threadIdx.x;
    const int bt   = blockIdx.x >> 3;
    const int ct   = blockIdx.x & 7;
    const int rb   = bt * 8;          // first batch row of this CTA
    const int j0   = ct * 32;         // first hidden column of this CTA

    const int warp = tid >> 5;
    const int lane = tid & 31;
    const int cg   = warp % 3;        // 0=F, 1=O, 2=Htmp
    const int kh   = warp / 3;        // k half
    const int col  = cg * 32 + lane;  // 0..95 within the 96 gate columns

    // --- detect int64 vs int32 token buffer -------------------------------
    const int* Xi = (const int*)Xraw;
    bool is64 = true;
#pragma unroll
    for (int i = 0; i < 16; i++)
        if (Xi[2 * i + 1] != 0) is64 = false;
    const long long* Xl = (const long long*)Xraw;

    // --- load the W_h slice into SMEM (96 gate rows x 256 k, as float4) ---
    for (int i = tid; i < 64 * 96; i += 192) {
        int k4 = i / 96, c = i % 96;
        int gsel = c >> 5, j = c & 31;
        int grow = (gsel == 0 ? 0 : (gsel == 1 ? 512 : 768)) + j0 + j;
        Wsm[i] = *(const ulonglong2*)(Ww + grow * 512 + k4 * 4);
    }
    // --- zero C state ------------------------------------------------------
    if (tid < 64) {
#pragma unroll
        for (int i = 0; i < 4; i++) Csm[i * 64 + tid] = 0.0f;
    }
    __syncthreads();

    const float* T = g_T;

    for (int t = 0; t < LSEQ; t++) {
        const int cur = t & 1, nxt = cur ^ 1;

        // ---- 1. tokens for this step (independent of the barrier) --------
        if (tid < 8) {
            long long v = is64 ? Xl[(rb + tid) * LSEQ + t]
                               : (long long)Xi[(rb + tid) * LSEQ + t];
            tok[tid] = (int)v;
        }
        __syncthreads();

        // ---- 2. prefetch Gx from the token table (hidden behind barrier) -
        float gxF[4], gxO[4], gxH[4];
        if (tid < 64) {
#pragma unroll
            for (int i = 0; i < 4; i++) {
                int e = i * 64 + tid;
                int r = e >> 5, j = e & 31;
                const float* Tr = T + (long long)tok[r] * G3 + j0 + j;
                gxF[i] = __ldg(Tr);
                gxO[i] = __ldg(Tr + 256);
                gxH[i] = __ldg(Tr + 512);
            }
        }

        // ---- 3. wait for H_t ----------------------------------------------
        if (tid == 0) {
            unsigned target = 128u * (unsigned)t;
            while (ld_acq(&g_ctr) < target) { }
        }
        __syncthreads();

        // ---- 4. load H_t (8 rows x 256) into SMEM via L2 (ld.cg) ----------
        {
            const float* hb = g_Hbuf[cur];
            for (int i = tid; i < 512; i += 192) {
                int r = i >> 6, k4 = i & 63;
                float4 v = __ldcg((const float4*)(hb + (rb + r) * HDIM + k4 * 4));
                ((float4*)Hsm)[i] = v;
            }
        }
        __syncthreads();

        // ---- 5. k-loop: partial G over this thread's k-half ---------------
        unsigned long long acc2[8];
#pragma unroll
        for (int r = 0; r < 8; r++) acc2[r] = 0ull;

        const int kbase = kh * 32;
#pragma unroll 4
        for (int u = 0; u < 32; u++) {
            int kk4 = kbase + u;
            ulonglong2 wv = Wsm[kk4 * 96 + col];
#pragma unroll
            for (int r = 0; r < 8; r++) {
                ulonglong2 hv = Hsm[r * 64 + kk4];
                acc2[r] = ffma2(wv.x, hv.x, acc2[r]);
                acc2[r] = ffma2(wv.y, hv.y, acc2[r]);
            }
        }
#pragma unroll
        for (int r = 0; r < 8; r++) {
            float2 f = ull2f2(acc2[r]);
            Gsm[(kh * 8 + r) * 96 + col] = f.x + f.y;
        }
        __syncthreads();

        // ---- 6. epilogue: gates, C update, H_new --------------------------
        if (tid < 64) {
            float* hn_out = g_Hbuf[nxt];
#pragma unroll
            for (int i = 0; i < 4; i++) {
                int e = i * 64 + tid;
                int r = e >> 5, j = e & 31;
                float gF = Gsm[r * 96 + j]      + Gsm[(8 + r) * 96 + j]      + gxF[i];
                float gO = Gsm[r * 96 + 32 + j] + Gsm[(8 + r) * 96 + 32 + j] + gxO[i];
                float gH = Gsm[r * 96 + 64 + j] + Gsm[(8 + r) * 96 + 64 + j] + gxH[i];
                float F  = sigmoidf_(gF);
                float O  = sigmoidf_(gO);
                float Ht = tanhf(gH);
                float c  = Csm[r * 32 + j];
                c = F * c + O * Ht;            // faithful: uses O, not I
                Csm[r * 32 + j] = c;
                float hn = O * tanhf(c);
                __stcg(hn_out + (rb + r) * HDIM + j0 + j, hn);
                if (t == LSEQ - 1)
                    out[(rb + r) * HDIM + j0 + j] = hn;
            }
            __threadfence();   // make H_new stores device-visible
        }
        __syncthreads();

        // ---- 7. arrive -----------------------------------------------------
        if (tid == 0) red_add_rel(&g_ctr, 1u);
    }
}

// ---------------------------------------------------------------------------
// launcher
// ---------------------------------------------------------------------------
extern "C" void kernel_launch(void* const* d_in, const int* in_sizes, int n_in,
                              void* d_out, int out_size)
{
    (void)in_sizes; (void)n_in; (void)out_size;
    const void*  X  = d_in[0];
    const float* E  = (const float*)d_in[1];
    const float* Ww = (const float*)d_in[2];
    const float* Wb = (const float*)d_in[3];
    float*       out = (float*)d_out;

    cudaFuncSetAttribute(lstm_kernel,
                         cudaFuncAttributeMaxDynamicSharedMemorySize,
                         SMEM_TOTAL);

    table_kernel<<<dim3(VOC / 64, G3 / 64), 256>>>(E, Ww, Wb);
    lstm_kernel<<<128, 192, SMEM_TOTAL>>>(X, Ww, out);
}